// round 3
// baseline (speedup 1.0000x reference)
#include <cuda_runtime.h>

#define T_STEPS 2048
#define BATCH   32
#define HID     256
#define INP     256

// Small scratch only (allocation-free rule: __device__ globals)
__device__ float g_WrT[HID * HID];   // W_rec transposed: [src][dst]
__device__ float g_WiT[INP * HID];   // W_in transposed:  [k][n]

// ---------------------------------------------------------------------------
// Transpose both weight matrices (tiny, one-time)
// ---------------------------------------------------------------------------
__global__ void transpose_weights(const float* __restrict__ Wi,
                                  const float* __restrict__ Wr) {
    int s = blockIdx.x;   // source (column) index
    int h = threadIdx.x;  // dest row index
    g_WiT[s * HID + h] = Wi[h * INP + s];
    g_WrT[s * HID + h] = Wr[h * HID + s];
}

// ---------------------------------------------------------------------------
// SGEMM: C[m,n] = sum_k A[m,k] * WiT[k,n]
// A = input reshaped (T*B, 256); C = xw buffer == d_out spike region (in-place
// reuse: lif_scan reads xw[t,b,h] before overwriting out[t,b,h] in the same
// thread, so no conflict).
// 128x128 block tile, k-step 8, double-buffered smem, 8x8 per-thread microtile
// ---------------------------------------------------------------------------
__global__ __launch_bounds__(256) void sgemm_xw(const float* __restrict__ A,
                                                float* __restrict__ C) {
    __shared__ float As[2][8][128];
    __shared__ float Bs[2][8][128];

    const int tid = threadIdx.x;
    const int tx = tid & 15;        // 0..15 (n)
    const int ty = tid >> 4;        // 0..15 (m)
    const int bm = blockIdx.x * 128;
    const int bn = blockIdx.y * 128;

    // A tile load: 128 rows x 8 k, one float4 per thread
    const int arow = tid >> 1;          // 0..127
    const int acol = (tid & 1) * 4;     // 0 or 4
    // B tile load: 8 rows x 128 n, one float4 per thread
    const int brow = tid >> 5;          // 0..7
    const int bcol = (tid & 31) * 4;    // 0..124

    const float* Ap = A + (size_t)(bm + arow) * INP + acol;
    const float* Bp = g_WiT + brow * HID + bn + bcol;

    float4 a = *(const float4*)Ap;
    float4 b = *(const float4*)Bp;
    As[0][acol + 0][arow] = a.x;
    As[0][acol + 1][arow] = a.y;
    As[0][acol + 2][arow] = a.z;
    As[0][acol + 3][arow] = a.w;
    *(float4*)&Bs[0][brow][bcol] = b;
    __syncthreads();

    float acc[8][8];
#pragma unroll
    for (int i = 0; i < 8; ++i)
#pragma unroll
        for (int j = 0; j < 8; ++j) acc[i][j] = 0.0f;

    for (int kt = 0; kt < 32; ++kt) {
        const int cur = kt & 1;
        float4 an, bn4;
        if (kt < 31) {
            an  = *(const float4*)(Ap + (kt + 1) * 8);
            bn4 = *(const float4*)(Bp + (size_t)(kt + 1) * 8 * HID);
        }
#pragma unroll
        for (int k = 0; k < 8; ++k) {
            float4 a0 = *(const float4*)&As[cur][k][ty * 4];
            float4 a1 = *(const float4*)&As[cur][k][64 + ty * 4];
            float4 b0 = *(const float4*)&Bs[cur][k][tx * 4];
            float4 b1 = *(const float4*)&Bs[cur][k][64 + tx * 4];
            float av[8] = {a0.x, a0.y, a0.z, a0.w, a1.x, a1.y, a1.z, a1.w};
            float bv[8] = {b0.x, b0.y, b0.z, b0.w, b1.x, b1.y, b1.z, b1.w};
#pragma unroll
            for (int i = 0; i < 8; ++i)
#pragma unroll
                for (int j = 0; j < 8; ++j)
                    acc[i][j] = fmaf(av[i], bv[j], acc[i][j]);
        }
        if (kt < 31) {
            const int nxt = cur ^ 1;
            As[nxt][acol + 0][arow] = an.x;
            As[nxt][acol + 1][arow] = an.y;
            As[nxt][acol + 2][arow] = an.z;
            As[nxt][acol + 3][arow] = an.w;
            *(float4*)&Bs[nxt][brow][bcol] = bn4;
        }
        __syncthreads();
    }

#pragma unroll
    for (int i = 0; i < 8; ++i) {
        const int row = bm + ((i < 4) ? (ty * 4 + i) : (64 + ty * 4 + (i - 4)));
        float4 c0 = {acc[i][0], acc[i][1], acc[i][2], acc[i][3]};
        float4 c1 = {acc[i][4], acc[i][5], acc[i][6], acc[i][7]};
        *(float4*)&C[(size_t)row * HID + bn + tx * 4]      = c0;
        *(float4*)&C[(size_t)row * HID + bn + 64 + tx * 4] = c1;
    }
}

// ---------------------------------------------------------------------------
// LIF scan: one block per batch element, 256 threads = one per hidden unit.
// Recurrent matvec = sparse sum over spike list (z is binary).
// xw buffer == out buffer (read-then-overwrite, same thread, same index).
// State-update rounding forced non-contracted to track the reference.
// ---------------------------------------------------------------------------
__global__ __launch_bounds__(256) void lif_scan(
    const float* __restrict__ z0, const float* __restrict__ v0,
    const float* __restrict__ i0,
    float* __restrict__ out, float* __restrict__ zf,
    float* __restrict__ vf, float* __restrict__ sf)
{
    const int b = blockIdx.x;
    const int h = threadIdx.x;
    const int lane = h & 31;
    const int wid  = h >> 5;

    __shared__ unsigned       masks[8];
    __shared__ unsigned short slist[256];

    float v   = v0[b * HID + h];
    float syn = i0[b * HID + h];
    float z   = z0[b * HID + h];

    float*       xop = out + b * HID + h;   // xw in, spikes out (in place)
    const float* wr  = g_WrT + h;

    for (int t = 0; t < T_STEPS; ++t) {
        const unsigned m = __ballot_sync(0xffffffffu, z > 0.0f);
        const float xwv = xop[(size_t)t * (BATCH * HID)];   // load early
        if (lane == 0) masks[wid] = m;
        __syncthreads();

        int base = 0, total = 0;
#pragma unroll
        for (int w = 0; w < 8; ++w) {
            const int c = __popc(masks[w]);
            if (w < wid) base += c;
            total += c;
        }
        if (z > 0.0f)
            slist[base + __popc(m & ((1u << lane) - 1u))] = (unsigned short)h;
        __syncthreads();

        // sparse recurrent gather: rec = sum over spiking src of W_rec[h, src]
        float r0 = 0.0f, r1 = 0.0f, r2 = 0.0f, r3 = 0.0f;
        int j = 0;
        for (; j + 4 <= total; j += 4) {
            const int s0 = slist[j], s1 = slist[j + 1];
            const int s2 = slist[j + 2], s3 = slist[j + 3];
            r0 += __ldg(wr + s0 * HID);
            r1 += __ldg(wr + s1 * HID);
            r2 += __ldg(wr + s2 * HID);
            r3 += __ldg(wr + s3 * HID);
        }
        for (; j < total; ++j) r0 += __ldg(wr + slist[j] * HID);
        const float rec = (r0 + r1) + (r2 + r3);

        // LIF update (match reference op order; no FMA contraction)
        const float vdec = __fadd_rn(v, __fmul_rn(0.1f, __fadd_rn(__fsub_rn(0.0f, v), syn)));
        const float idec = __fsub_rn(syn, __fmul_rn(0.2f, syn));
        const float zn   = (vdec - 1.0f > 0.0f) ? 1.0f : 0.0f;
        v   = (zn > 0.0f) ? 0.0f : vdec;
        syn = __fadd_rn(__fadd_rn(idec, xwv), rec);

        xop[(size_t)t * (BATCH * HID)] = zn;   // overwrite xw with spike
        z = zn;
    }

    zf[b * HID + h] = z;
    vf[b * HID + h] = v;
    sf[b * HID + h] = syn;
}

// ---------------------------------------------------------------------------
extern "C" void kernel_launch(void* const* d_in, const int* in_sizes, int n_in,
                              void* d_out, int out_size) {
    const float* input = (const float*)d_in[0];  // (T, B, IN)
    const float* z0    = (const float*)d_in[1];  // (B, H)
    const float* v0    = (const float*)d_in[2];
    const float* i0    = (const float*)d_in[3];
    const float* Wi    = (const float*)d_in[4];  // (H, IN)
    const float* Wr    = (const float*)d_in[5];  // (H, H)

    float* out = (float*)d_out;                         // (T, B, H) spikes
    float* zf  = out + (size_t)T_STEPS * BATCH * HID;   // (B, H)
    float* vf  = zf + BATCH * HID;
    float* sf  = vf + BATCH * HID;

    transpose_weights<<<HID, HID>>>(Wi, Wr);
    sgemm_xw<<<dim3((T_STEPS * BATCH) / 128, HID / 128), 256>>>(input, out);
    lif_scan<<<BATCH, HID>>>(z0, v0, i0, out, zf, vf, sf);
}